// round 16
// baseline (speedup 1.0000x reference)
#include <cuda_runtime.h>
#include <cuda_bf16.h>
#include <math.h>
#include <stdint.h>

#define HH       256
#define NHEADS   8
#define MAX_N    1024
#define MAX_EDGES 600000
#define ETILE    256
#define SUB      32
#define GSPLIT   8

// ---------------- scratch (device globals; no allocation allowed) -------------
__device__ __align__(16) int    g_cnt2[MAX_N * SUB];
__device__ __align__(16) int    g_cur2[MAX_N * SUB];
__device__ int    g_roff[MAX_N + 1];
__device__ int    g_deg1[MAX_N];
__device__ int    g_deg2[MAX_N];
__device__ float  g_asum[MAX_N * 3];
__device__ float4 g_epack[MAX_EDGES];          // (src_as_float, a0, a1, a2)
__device__ float  g_h [MAX_N * HH];
__device__ float  g_xl[MAX_N * HH];
__device__ float  g_xr[MAX_N * HH];
__device__ float  g_A [MAX_N * HH];
__device__ float  g_B [MAX_N * HH];
__device__ float  g_pacc[MAX_N * GSPLIT * HH];     // gat partials
__device__ float  g_pden[MAX_N * GSPLIT * NHEADS];
__device__ __align__(16) __nv_bfloat16 g_w2h[128 * 256];   // W2^T hi  [n][k]
__device__ __align__(16) __nv_bfloat16 g_w2l[128 * 256];   // W2^T lo
__device__ __align__(16) __nv_bfloat16 g_hh[MAX_N * HH];   // h hi/lo split
__device__ __align__(16) __nv_bfloat16 g_hl[MAX_N * HH];
__device__ __align__(16) __nv_bfloat16 g_wth[5 * 512 * HH]; // W^T hi: 4 layers
__device__ __align__(16) __nv_bfloat16 g_wtl[5 * 512 * HH]; //  (Wl|Wr) + (p1a|p1b)

// bf16 HMMA (sm_80+, no arch-feature suffix -> compiles for base sm_103)
__device__ __forceinline__ void mma16816(float* d, const uint32_t* a,
                                         uint32_t b0, uint32_t b1) {
    asm volatile(
        "mma.sync.aligned.m16n8k16.row.col.f32.bf16.bf16.f32 "
        "{%0,%1,%2,%3}, {%4,%5,%6,%7}, {%8,%9}, {%0,%1,%2,%3};"
        : "+f"(d[0]), "+f"(d[1]), "+f"(d[2]), "+f"(d[3])
        : "r"(a[0]), "r"(a[1]), "r"(a[2]), "r"(a[3]), "r"(b0), "r"(b1));
}
// ldmatrix x4: one instruction loads a 16x16 bf16 fragment (4 8x8 tiles)
__device__ __forceinline__ void ldmx4(uint32_t* r, const void* p) {
    uint32_t a = (uint32_t)__cvta_generic_to_shared(p);
    asm volatile("ldmatrix.sync.aligned.m8n8.x4.shared.b16 {%0,%1,%2,%3}, [%4];"
                 : "=r"(r[0]), "=r"(r[1]), "=r"(r[2]), "=r"(r[3]) : "r"(a));
}

// ---------------- setup kernels ------------------------------------------------
__global__ void k_embinit(const float* __restrict__ x, const float* __restrict__ W,
                          const float* __restrict__ b) {
    int n = blockIdx.x, t = threadIdx.x;
    float hv = x[n] * W[t] + b[t];
    g_h[n * HH + t] = hv;
    __nv_bfloat16 hi = __float2bfloat16(hv);
    g_hh[n * HH + t] = hi;
    g_hl[n * HH + t] = __float2bfloat16(hv - __bfloat162float(hi));
    if (t < SUB) g_cnt2[n * SUB + t] = 0;
    if (t == 32) { g_deg1[n] = 0; g_deg2[n] = 0; }
    if (t == 33) {
        g_asum[3 * n] = 0.f; g_asum[3 * n + 1] = 0.f; g_asum[3 * n + 2] = 0.f;
    }
}

__global__ void k_edge_stats(const int* __restrict__ ei, const float* __restrict__ ea,
                             int E) {
    int e = blockIdx.x * blockDim.x + threadIdx.x;
    if (e >= E) return;
    int s = ei[e], d = ei[E + e];
    float a0 = ea[3 * e], a1 = ea[3 * e + 1], a2 = ea[3 * e + 2];
    atomicAdd(&g_cnt2[d * SUB + (e & (SUB - 1))], 1);
    atomicAdd(&g_asum[3 * d + 0], a0);
    atomicAdd(&g_asum[3 * d + 1], a1);
    atomicAdd(&g_asum[3 * d + 2], a2);
    int best = 0; float bv = a0;
    if (a1 > bv) { best = 1; bv = a1; }
    if (a2 > bv) { best = 2; }
    if (best == 1) { atomicAdd(&g_deg1[s], 1); atomicAdd(&g_deg1[d], 1); }
    else if (best == 2) { atomicAdd(&g_deg2[s], 1); atomicAdd(&g_deg2[d], 1); }
}

__global__ void k_scan(int N) {
    __shared__ int sc[1024];
    int t = threadIdx.x;
    int4 v[8];
    int cnt = 0;
    if (t < N) {
        const int4* p = (const int4*)(g_cnt2 + t * SUB);
#pragma unroll
        for (int i = 0; i < 8; i++) v[i] = p[i];
#pragma unroll
        for (int i = 0; i < 8; i++) cnt += v[i].x + v[i].y + v[i].z + v[i].w;
    }
    int len = (t < N) ? (cnt + 1) : 0;
    sc[t] = len;
    __syncthreads();
    for (int off = 1; off < 1024; off <<= 1) {
        int u = (t >= off) ? sc[t - off] : 0;
        __syncthreads();
        sc[t] += u;
        __syncthreads();
    }
    if (t < N) {
        int incl = sc[t];
        int excl = incl - len;
        g_roff[t + 1] = incl;
        if (t == 0) g_roff[0] = 0;
        int off = excl;
        int4* q = (int4*)(g_cur2 + t * SUB);
#pragma unroll
        for (int i = 0; i < 8; i++) {
            int4 o;
            o.x = off; off += v[i].x;
            o.y = off; off += v[i].y;
            o.z = off; off += v[i].z;
            o.w = off; off += v[i].w;
            q[i] = o;
        }
        int slot = excl + cnt;
        float c = fmaxf((float)cnt, 1.0f);
        g_epack[slot] = make_float4(__int_as_float(t),
                                    g_asum[3 * t + 0] / c,
                                    g_asum[3 * t + 1] / c,
                                    g_asum[3 * t + 2] / c);
    }
}

__global__ void k_scatter(const int* __restrict__ ei, const float* __restrict__ ea,
                          int E) {
    int e = blockIdx.x * blockDim.x + threadIdx.x;
    if (e >= E) return;
    int s = ei[e], d = ei[E + e];
    int pos = atomicAdd(&g_cur2[d * SUB + (e & (SUB - 1))], 1);
    g_epack[pos] = make_float4(__int_as_float(s), ea[3 * e], ea[3 * e + 1], ea[3 * e + 2]);
}

// W2^T bf16 hi/lo split: g_w2h/l[n][k] = split(p2W[k][n])
__global__ void k_wsplit(const float* __restrict__ p2W) {
    int n = blockIdx.x, k = threadIdx.x;
    float w = p2W[k * 128 + n];
    __nv_bfloat16 hi = __float2bfloat16(w);
    g_w2h[n * 256 + k] = hi;
    g_w2l[n * 256 + k] = __float2bfloat16(w - __bfloat162float(hi));
}

// split all node-linear weights (transposed [n][k]) into bf16 hi/lo:
// slot l<4: cols = (Wl[l] | Wr[l]); slot 4: cols = (p1W[:256] | p1W[256:])
__global__ void k_wsplit_all(const float* __restrict__ Wl,
                             const float* __restrict__ Wr,
                             const float* __restrict__ p1W) {
    int n = blockIdx.x, l = blockIdx.y, k = threadIdx.x;
    float w;
    if (l < 4) {
        w = (n < 256) ? Wl[((size_t)l * 256 + k) * 256 + n]
                      : Wr[((size_t)l * 256 + k) * 256 + (n - 256)];
    } else {
        w = (n < 256) ? p1W[(size_t)k * 256 + n]
                      : p1W[(size_t)(k + 256) * 256 + (n - 256)];
    }
    __nv_bfloat16 hi = __float2bfloat16(w);
    size_t idx = ((size_t)l * 512 + n) * HH + k;
    g_wth[idx] = hi;
    g_wtl[idx] = __float2bfloat16(w - __bfloat162float(hi));
}

// ---------------- node linear layers via bf16-split HMMA ----------------------
// out[m][n] (128x128 tile) = H[m][:] . W^T[n][:]  (3-term hi/lo split) + bias.
// outsel: 0 -> (g_xl | g_xr), 1 -> (g_A | g_B).
#define QSTR 40   // padded bf16 row stride (80B: conflict-free, 16B-aligned)
__global__ void __launch_bounds__(256)
k_lin_mma(int wslot, int outsel,
          const float* __restrict__ b0, const float* __restrict__ b1, int N) {
    __shared__ __align__(16) __nv_bfloat16 Ah[128][QSTR], Al[128][QSTR];
    __shared__ __align__(16) __nv_bfloat16 Wh[128][QSTR], Wlo[128][QSTR];
    int t = threadIdx.x;
    int lane = t & 31, wid = t >> 5;
    int warp_m = wid & 3, warp_n = wid >> 2;
    int mbase = warp_m * 32, nbase = warp_n * 64;
    int tm = blockIdx.x, tn = blockIdx.y;
    float* outp = (outsel == 0) ? ((tn < 2) ? g_xl : g_xr)
                                : ((tn < 2) ? g_A  : g_B);
    const float* bp = (tn < 2) ? b0 : b1;
    int ncb = (tn & 1) * 128;

    int pr = t >> 1, kh = t & 1;
    int hrow = tm * 128 + pr;
    if (hrow > N - 1) hrow = N - 1;
    const __nv_bfloat16* wrh = &g_wth[((size_t)wslot * 512 + tn * 128 + pr) * HH];
    const __nv_bfloat16* wrl = &g_wtl[((size_t)wslot * 512 + tn * 128 + pr) * HH];
    int lrow = lane & 15;                 // ldmatrix row within 16x16 fragment
    int lcol = (lane >> 4) << 3;          // 0 or 8

    float acc[2][8][4] = {};
    for (int cc = 0; cc < 8; cc++) {
        __syncthreads();
        int cb = cc * 32 + kh * 16;
        const uint2* ah = (const uint2*)&g_hh[(size_t)hrow * HH + cb];
        const uint2* al = (const uint2*)&g_hl[(size_t)hrow * HH + cb];
        const uint2* wh = (const uint2*)&wrh[cb];
        const uint2* wl = (const uint2*)&wrl[cb];
#pragma unroll
        for (int m = 0; m < 4; m++) {
            *(uint2*)&Ah[pr][kh * 16 + 4 * m]  = ah[m];
            *(uint2*)&Al[pr][kh * 16 + 4 * m]  = al[m];
            *(uint2*)&Wh[pr][kh * 16 + 4 * m]  = wh[m];
            *(uint2*)&Wlo[pr][kh * 16 + 4 * m] = wl[m];
        }
        __syncthreads();
#pragma unroll
        for (int k0 = 0; k0 < 32; k0 += 16) {
            uint32_t fah[2][4], fal[2][4];
#pragma unroll
            for (int mt = 0; mt < 2; mt++) {
                ldmx4(fah[mt], &Ah[mbase + mt * 16 + lrow][k0 + lcol]);
                ldmx4(fal[mt], &Al[mbase + mt * 16 + lrow][k0 + lcol]);
            }
#pragma unroll
            for (int ntp = 0; ntp < 4; ntp++) {
                uint32_t bh[4], blo[4];
                ldmx4(bh,  &Wh [nbase + ntp * 16 + lrow][k0 + lcol]);
                ldmx4(blo, &Wlo[nbase + ntp * 16 + lrow][k0 + lcol]);
#pragma unroll
                for (int sb = 0; sb < 2; sb++) {
                    int nt = 2 * ntp + sb;
#pragma unroll
                    for (int mt = 0; mt < 2; mt++) {
                        mma16816(acc[mt][nt], fah[mt], bh[sb],  bh[2 + sb]);
                        mma16816(acc[mt][nt], fah[mt], blo[sb], blo[2 + sb]);
                        mma16816(acc[mt][nt], fal[mt], bh[sb],  bh[2 + sb]);
                    }
                }
            }
        }
    }

    int rg = lane >> 2;
#pragma unroll
    for (int nt = 0; nt < 8; nt++) {
        int col = ncb + nbase + nt * 8 + (lane & 3) * 2;
        float bv0 = bp ? bp[col] : 0.f;
        float bv1 = bp ? bp[col + 1] : 0.f;
#pragma unroll
        for (int mt = 0; mt < 2; mt++) {
            int r0 = tm * 128 + mbase + mt * 16 + rg;
            if (r0 < N)
                *(float2*)&outp[(size_t)r0 * HH + col] =
                    make_float2(acc[mt][nt][0] + bv0, acc[mt][nt][1] + bv1);
            int r1 = r0 + 8;
            if (r1 < N)
                *(float2*)&outp[(size_t)r1 * HH + col] =
                    make_float2(acc[mt][nt][2] + bv0, acc[mt][nt][3] + bv1);
        }
    }
}

// GAT partial: grid (N, GSPLIT). Pure sums (no running max) -> partials combine.
__global__ void __launch_bounds__(128)
k_gatp(const float* __restrict__ We, const float* __restrict__ att, int l) {
    __shared__ float4 ep[ETILE];
    int n = blockIdx.x, sp = blockIdx.y, t = threadIdx.x;
    int lane = t & 31;
    int ch0 = 2 * t;
    int head = t >> 4;
    int hc = ch0 & 31;
    float2 xr2 = *(const float2*)&g_xr[n * HH + ch0];
    float att0 = att[(l * NHEADS + head) * 32 + hc];
    float att1 = att[(l * NHEADS + head) * 32 + hc + 1];
    float we00 = We[(l * 3 + 0) * HH + ch0], we01 = We[(l * 3 + 0) * HH + ch0 + 1];
    float we10 = We[(l * 3 + 1) * HH + ch0], we11 = We[(l * 3 + 1) * HH + ch0 + 1];
    float we20 = We[(l * 3 + 2) * HH + ch0], we21 = We[(l * 3 + 2) * HH + ch0 + 1];
    int r0 = g_roff[n], cnt_all = g_roff[n + 1] - r0;
    int e0 = r0 + (cnt_all * sp) / GSPLIT;
    int e1 = r0 + (cnt_all * (sp + 1)) / GSPLIT;

    float den = 0.f, acc0 = 0.f, acc1 = 0.f;
    for (int t0 = e0; t0 < e1; t0 += ETILE) {
        int cnt = min(ETILE, e1 - t0);
        __syncthreads();
        for (int k = t; k < cnt; k += 128) ep[k] = g_epack[t0 + k];
        __syncthreads();
#pragma unroll 2
        for (int g = 0; g < cnt; g += 4) {
            float2 xv[4];
            float al[4];
#pragma unroll
            for (int u = 0; u < 4; u++) {
                int idx = min(g + u, cnt - 1);
                float4 e = ep[idx];
                int s = __float_as_int(e.x);
                xv[u] = *(const float2*)&g_xl[s * HH + ch0];
                float s0 = xv[u].x + xr2.x + e.y * we00 + e.z * we10 + e.w * we20;
                float s1 = xv[u].y + xr2.y + e.y * we01 + e.z * we11 + e.w * we21;
                s0 = s0 > 0.f ? s0 : 0.2f * s0;
                s1 = s1 > 0.f ? s1 : 0.2f * s1;
                float v = s0 * att0 + s1 * att1;
                al[u] = (g + u < cnt) ? v : -1e30f;
            }
            float p0 = (lane & 8) ? al[2] : al[0];
            float q0 = (lane & 8) ? al[0] : al[2];
            float p1 = (lane & 8) ? al[3] : al[1];
            float q1 = (lane & 8) ? al[1] : al[3];
            p0 += __shfl_xor_sync(0xffffffffu, q0, 8);
            p1 += __shfl_xor_sync(0xffffffffu, q1, 8);
            float pa = (lane & 4) ? p1 : p0;
            float qa = (lane & 4) ? p0 : p1;
            pa += __shfl_xor_sync(0xffffffffu, qa, 4);
            pa += __shfl_xor_sync(0xffffffffu, pa, 2);
            pa += __shfl_xor_sync(0xffffffffu, pa, 1);
            float wexp = __expf(pa);                // 1 exp, then broadcast
            int base = lane & 16;
#pragma unroll
            for (int u = 0; u < 4; u++) {
                float w = __shfl_sync(0xffffffffu, wexp, base + (u << 2));
                den += w;
                acc0 = fmaf(w, xv[u].x, acc0);
                acc1 = fmaf(w, xv[u].y, acc1);
            }
        }
    }
    int pb = n * GSPLIT + sp;
    *(float2*)&g_pacc[pb * HH + ch0] = make_float2(acc0, acc1);
    if ((t & 15) == 0) g_pden[pb * NHEADS + head] = den;
}

// GAT combine: sum GSPLIT partials, normalize, residual + LayerNorm + ReLU.
// Also writes the bf16 hi/lo split of the new h for the next linear layer.
__global__ void __launch_bounds__(128)
k_gatc(const float* __restrict__ gb, const float* __restrict__ lng,
       const float* __restrict__ lnb, int l) {
    __shared__ float red[4];
    int n = blockIdx.x, t = threadIdx.x;
    int wid = t >> 5, lane = t & 31;
    int ch0 = 2 * t;
    int head = t >> 4;
    float acc0 = 0.f, acc1 = 0.f, den = 0.f;
#pragma unroll
    for (int s = 0; s < GSPLIT; s++) {
        int pb = n * GSPLIT + s;
        float2 a = *(const float2*)&g_pacc[pb * HH + ch0];
        acc0 += a.x; acc1 += a.y;
        den += g_pden[pb * NHEADS + head];
    }
    float inv = 1.0f / den;
    float2 hres = *(const float2*)&g_h[n * HH + ch0];
    float o0 = acc0 * inv + gb[l * HH + ch0]     + hres.x;
    float o1 = acc1 * inv + gb[l * HH + ch0 + 1] + hres.y;

    float v = o0 + o1;
#pragma unroll
    for (int o = 16; o > 0; o >>= 1) v += __shfl_xor_sync(0xffffffffu, v, o);
    if (lane == 0) red[wid] = v;
    __syncthreads();
    float mu = (red[0] + red[1] + red[2] + red[3]) * (1.0f / HH);
    float d0 = o0 - mu, d1 = o1 - mu;
    float q = d0 * d0 + d1 * d1;
#pragma unroll
    for (int o = 16; o > 0; o >>= 1) q += __shfl_xor_sync(0xffffffffu, q, o);
    __syncthreads();
    if (lane == 0) red[wid] = q;
    __syncthreads();
    float var = (red[0] + red[1] + red[2] + red[3]) * (1.0f / HH);
    float rstd = rsqrtf(var + 1e-5f);
    float y0 = fmaxf(d0 * rstd * lng[l * HH + ch0]     + lnb[l * HH + ch0], 0.f);
    float y1 = fmaxf(d1 * rstd * lng[l * HH + ch0 + 1] + lnb[l * HH + ch0 + 1], 0.f);
    *(float2*)&g_h[n * HH + ch0] = make_float2(y0, y1);
    __nv_bfloat16 h0 = __float2bfloat16(y0), h1 = __float2bfloat16(y1);
    __nv_bfloat162 hh; hh.x = h0; hh.y = h1;
    *(__nv_bfloat162*)&g_hh[n * HH + ch0] = hh;
    __nv_bfloat162 hl;
    hl.x = __float2bfloat16(y0 - __bfloat162float(h0));
    hl.y = __float2bfloat16(y1 - __bfloat162float(h1));
    *(__nv_bfloat162*)&g_hl[n * HH + ch0] = hl;
}

// graph pooling + value head + Potts energy
__global__ void k_graph(const float* __restrict__ v1W, const float* __restrict__ v1b,
                        const float* __restrict__ v2W, const float* __restrict__ v2b,
                        const float* __restrict__ coup, float* __restrict__ out,
                        int N, long long P) {
    __shared__ float gr[2 * HH];
    __shared__ float psum[2][HH];
    __shared__ float pmax[2][HH];
    __shared__ float sred[512];
    int t = threadIdx.x;
    int half = t >> 8, ch = t & 255;
    int nh = N >> 1;
    {
        float s = 0.f, mx = -1e30f;
        for (int n = half * nh; n < (half + 1) * nh; n++) {
            float v = g_h[n * HH + ch];
            s += v; mx = fmaxf(mx, v);
        }
        psum[half][ch] = s; pmax[half][ch] = mx;
    }
    __syncthreads();
    if (t < HH) {
        gr[t] = (psum[0][t] + psum[1][t]) / (float)N;
        gr[HH + t] = fmaxf(pmax[0][t], pmax[1][t]);
    }
    __syncthreads();
    float contrib = 0.f;
    if (t < HH) {
        float a = v1b[t];
        for (int c = 0; c < 2 * HH; c++) a = fmaf(gr[c], v1W[c * HH + t], a);
        a = fmaxf(a, 0.f);
        contrib = a * v2W[t];
    }
    sred[t] = contrib;
    __syncthreads();
    for (int off = 256; off > 0; off >>= 1) {
        if (t < off) sred[t] += sred[t + off];
        __syncthreads();
    }
    if (t == 0) out[P] = sred[0] + v2b[0];

    float e = 0.f;
    for (int n = t; n < N; n += 512) {
        float d1 = (float)g_deg1[n], d2 = (float)g_deg2[n];
        e += d1 * d1 + d2 * d2;
    }
    __syncthreads();
    sred[t] = e;
    __syncthreads();
    for (int off = 256; off > 0; off >>= 1) {
        if (t < off) sred[t] += sred[t + off];
        __syncthreads();
    }
    if (t == 0) out[P + 1] = coup[0] * sred[0] / (2.0f * (float)N);
}

// ---------------- all-pairs MLP: bf16-split HMMA, register-prefetch pipeline ---
// 16 k-chunks of 16; each thread owns pair-row pr=t>>1, k-half kh=t&1 (8 A + 8 B
// floats + 8+8 W bf16 per chunk). LDGs for chunk cc+1 issue BEFORE chunk cc's
// MMA phase -> global latency hidden behind split+MMA+barrier.
#define PST 24    // bf16 row stride (48B: 16B-aligned, ldmatrix conflict-free)
__global__ void __launch_bounds__(256)
k_pairs_mma(const float* __restrict__ p2b, const float* __restrict__ p3W,
            const float* __restrict__ p3b, float* __restrict__ out,
            int N, long long P) {
    __shared__ __align__(16) __nv_bfloat16 Qh[128][PST], Ql[128][PST];
    __shared__ __align__(16) __nv_bfloat16 Wh[128][PST], Wl[128][PST];
    __shared__ int si[128], sj[128];
    __shared__ float eps[128][2];
    int t = threadIdx.x;
    int lane = t & 31, wid = t >> 5;
    int warp_m = wid & 3, warp_n = wid >> 2;
    int mbase = warp_m * 32, nbase = warp_n * 64;
    long long pbase = (long long)blockIdx.x * 128;

    if (t < 128) {
        long long p = pbase + t;
        if (p > P - 1) p = P - 1;
        float tn = 2.0f * N - 1.0f;
        float disc = fmaxf(tn * tn - 8.0f * (float)p, 0.0f);
        int i = (int)((tn - sqrtf(disc)) * 0.5f);
        if (i < 0) i = 0;
        if (i > N - 2) i = N - 2;
        while ((long long)(i + 1) * (2 * N - 2 - i) / 2 <= p) i++;
        while ((long long)i * (2 * N - 1 - i) / 2 > p) i--;
        int j = i + 1 + (int)(p - (long long)i * (2 * N - 1 - i) / 2);
        si[t] = i; sj[t] = j;
    }
    __syncthreads();

    int pr = t >> 1, kh = t & 1;
    size_t ib = (size_t)si[pr] * HH + kh * 8;
    size_t jb = (size_t)sj[pr] * HH + kh * 8;
    size_t wb = (size_t)pr * 256 + kh * 8;
    int lrow = lane & 15;
    int lcol = (lane >> 4) << 3;

    // prefetch chunk 0
    float4 pa0 = *(const float4*)&g_A[ib];
    float4 pa1 = *(const float4*)&g_A[ib + 4];
    float4 pb0 = *(const float4*)&g_B[jb];
    float4 pb1 = *(const float4*)&g_B[jb + 4];
    uint4  pwh = *(const uint4*)&g_w2h[wb];
    uint4  pwl = *(const uint4*)&g_w2l[wb];

    float acc[2][8][4] = {};
    for (int cc = 0; cc < 16; cc++) {
        __syncthreads();                  // prev MMA done: Qh/Wh free
        // split current chunk into Qh/Ql; store W
        float q0 = fmaxf(pa0.x + pb0.x, 0.f), q1 = fmaxf(pa0.y + pb0.y, 0.f);
        float q2 = fmaxf(pa0.z + pb0.z, 0.f), q3 = fmaxf(pa0.w + pb0.w, 0.f);
        float q4 = fmaxf(pa1.x + pb1.x, 0.f), q5 = fmaxf(pa1.y + pb1.y, 0.f);
        float q6 = fmaxf(pa1.z + pb1.z, 0.f), q7 = fmaxf(pa1.w + pb1.w, 0.f);
        __nv_bfloat162 h01 = __floats2bfloat162_rn(q0, q1);
        __nv_bfloat162 h23 = __floats2bfloat162_rn(q2, q3);
        __nv_bfloat162 h45 = __floats2bfloat162_rn(q4, q5);
        __nv_bfloat162 h67 = __floats2bfloat162_rn(q6, q7);
        __nv_bfloat162 l01 = __floats2bfloat162_rn(q0 - __bfloat162float(h01.x),
                                                   q1 - __bfloat162float(h01.y));
        __nv_bfloat162 l23 = __floats2bfloat162_rn(q2 - __bfloat162float(h23.x),
                                                   q3 - __bfloat162float(h23.y));
        __nv_bfloat162 l45 = __floats2bfloat162_rn(q4 - __bfloat162float(h45.x),
                                                   q5 - __bfloat162float(h45.y));
        __nv_bfloat162 l67 = __floats2bfloat162_rn(q6 - __bfloat162float(h67.x),
                                                   q7 - __bfloat162float(h67.y));
        *(uint4*)&Qh[pr][kh * 8] = make_uint4(*(uint32_t*)&h01, *(uint32_t*)&h23,
                                              *(uint32_t*)&h45, *(uint32_t*)&h67);
        *(uint4*)&Ql[pr][kh * 8] = make_uint4(*(uint32_t*)&l01, *(uint32_t*)&l23,
                                              *(uint32_t*)&l45, *(uint32_t*)&l67);
        *(uint4*)&Wh[pr][kh * 8] = pwh;
        *(uint4*)&Wl[pr][kh * 8] = pwl;
        // issue next chunk's LDGs (latency hidden behind barrier + MMA)
        if (cc + 1 < 16) {
            size_t off = (size_t)(cc + 1) * 16;
            pa0 = *(const float4*)&g_A[ib + off];
            pa1 = *(const float4*)&g_A[ib + off + 4];
            pb0 = *(const float4*)&g_B[jb + off];
            pb1 = *(const float4*)&g_B[jb + off + 4];
            pwh = *(const uint4*)&g_w2h[wb + off];
            pwl = *(const uint4*)&g_w2l[wb + off];
        }
        __syncthreads();
        // MMA on chunk cc (single 16-k tile)
        uint32_t ah[2][4], al[2][4];
#pragma unroll
        for (int mt = 0; mt < 2; mt++) {
            ldmx4(ah[mt], &Qh[mbase + mt * 16 + lrow][lcol]);
            ldmx4(al[mt], &Ql[mbase + mt * 16 + lrow][lcol]);
        }
#pragma unroll
        for (int ntp = 0; ntp < 4; ntp++) {
            uint32_t bh[4], blo[4];
            ldmx4(bh,  &Wh[nbase + ntp * 16 + lrow][lcol]);
            ldmx4(blo, &Wl[nbase + ntp * 16 + lrow][lcol]);
#pragma unroll
            for (int sb = 0; sb < 2; sb++) {
                int nt = 2 * ntp + sb;
#pragma unroll
                for (int mt = 0; mt < 2; mt++) {
                    mma16816(acc[mt][nt], ah[mt], bh[sb],  bh[2 + sb]);
                    mma16816(acc[mt][nt], ah[mt], blo[sb], blo[2 + sb]);
                    mma16816(acc[mt][nt], al[mt], bh[sb],  bh[2 + sb]);
                }
            }
        }
    }

    float pA0 = 0.f, pA1 = 0.f, pB0 = 0.f, pB1 = 0.f;
#pragma unroll
    for (int nt = 0; nt < 8; nt++) {
#pragma unroll
        for (int v = 0; v < 2; v++) {
            int col = nbase + nt * 8 + (lane & 3) * 2 + v;
            float b2 = p2b[col], w3 = p3W[col];
            pA0 = fmaf(fmaxf(acc[0][nt][v] + b2, 0.f), w3, pA0);
            pB0 = fmaf(fmaxf(acc[0][nt][2 + v] + b2, 0.f), w3, pB0);
            pA1 = fmaf(fmaxf(acc[1][nt][v] + b2, 0.f), w3, pA1);
            pB1 = fmaf(fmaxf(acc[1][nt][2 + v] + b2, 0.f), w3, pB1);
        }
    }
    pA0 += __shfl_xor_sync(0xffffffffu, pA0, 1);
    pA0 += __shfl_xor_sync(0xffffffffu, pA0, 2);
    pB0 += __shfl_xor_sync(0xffffffffu, pB0, 1);
    pB0 += __shfl_xor_sync(0xffffffffu, pB0, 2);
    pA1 += __shfl_xor_sync(0xffffffffu, pA1, 1);
    pA1 += __shfl_xor_sync(0xffffffffu, pA1, 2);
    pB1 += __shfl_xor_sync(0xffffffffu, pB1, 1);
    pB1 += __shfl_xor_sync(0xffffffffu, pB1, 2);
    if ((lane & 3) == 0) {
        int g = lane >> 2;
        eps[mbase + g][warp_n]      = pA0;
        eps[mbase + g + 8][warp_n]  = pB0;
        eps[mbase + g + 16][warp_n] = pA1;
        eps[mbase + g + 24][warp_n] = pB1;
    }
    __syncthreads();
    if (t < 128) {
        long long pw = pbase + t;
        if (pw < P) out[pw] = eps[t][0] + eps[t][1] + p3b[0];
    }
}

// ---------------- launch ------------------------------------------------------
extern "C" void kernel_launch(void* const* d_in, const int* in_sizes, int n_in,
                              void* d_out, int out_size) {
    const float* x    = (const float*)d_in[0];
    const int*   ei   = (const int*)  d_in[1];
    const float* ea   = (const float*)d_in[2];
    const float* embW = (const float*)d_in[3];
    const float* embB = (const float*)d_in[4];
    const float* Wl   = (const float*)d_in[5];
    const float* bl   = (const float*)d_in[6];
    const float* Wr   = (const float*)d_in[7];
    const float* br   = (const float*)d_in[8];
    const float* We   = (const float*)d_in[9];
    const float* att  = (const float*)d_in[10];
    const float* gb   = (const float*)d_in[11];
    const float* lng  = (const float*)d_in[12];
    const float* lnb  = (const float*)d_in[13];
    const float* p1W  = (const float*)d_in[14];
    const float* p1b  = (const float*)d_in[15];
    const float* p2W  = (const float*)d_in[16];
    const float* p2b  = (const float*)d_in[17];
    const float* p3W  = (const float*)d_in[18];
    const float* p3b  = (const float*)d_in[19];
    const float* v1W  = (const float*)d_in[20];
    const float* v1b  = (const float*)d_in[21];
    const float* v2W  = (const float*)d_in[22];
    const float* v2b  = (const float*)d_in[23];
    const float* coup = (const float*)d_in[24];

    int N = in_sizes[0];
    int E = in_sizes[1] / 2;
    long long P = (long long)N * (N - 1) / 2;
    float* out = (float*)d_out;

    int rtiles = (N + 127) / 128;
    dim3 ling(rtiles, 4);

    k_embinit<<<N, 256>>>(x, embW, embB);
    k_edge_stats<<<(E + 255) / 256, 256>>>(ei, ea, E);
    k_scan<<<1, 1024>>>(N);
    k_scatter<<<(E + 255) / 256, 256>>>(ei, ea, E);
    k_wsplit_all<<<dim3(512, 5), 256>>>(Wl, Wr, p1W);
    k_wsplit<<<128, 256>>>(p2W);
    k_lin_mma<<<ling, 256>>>(0, 0, bl, br, N);
    for (int l = 0; l < 4; l++) {
        k_gatp<<<dim3(N, GSPLIT), 128>>>(We, att, l);
        k_gatc<<<N, 128>>>(gb, lng, lnb, l);
        if (l < 3)
            k_lin_mma<<<ling, 256>>>(l + 1, 0, bl + (l + 1) * HH,
                                     br + (l + 1) * HH, N);
    }
    k_graph<<<1, 512>>>(v1W, v1b, v2W, v2b, coup, out, N, P);
    k_lin_mma<<<ling, 256>>>(4, 1, p1b, (const float*)nullptr, N);
    int pblocks = (int)((P + 127) / 128);
    k_pairs_mma<<<pblocks, 256>>>(p2b, p3W, p3b, out, N, P);
}

// round 17
// speedup vs baseline: 1.0629x; 1.0629x over previous
#include <cuda_runtime.h>
#include <cuda_bf16.h>
#include <math.h>
#include <stdint.h>

#define HH       256
#define NHEADS   8
#define MAX_N    1024
#define MAX_EDGES 600000
#define ETILE    256
#define SUB      32
#define GSPLIT   8

// ---------------- scratch (device globals; no allocation allowed) -------------
__device__ __align__(16) int    g_cnt2[MAX_N * SUB];
__device__ __align__(16) int    g_cur2[MAX_N * SUB];
__device__ int    g_roff[MAX_N + 1];
__device__ int    g_deg1[MAX_N];
__device__ int    g_deg2[MAX_N];
__device__ float  g_asum[MAX_N * 3];
__device__ float4 g_epack[MAX_EDGES];          // (src_as_float, a0, a1, a2)
__device__ float  g_h [MAX_N * HH];
__device__ float  g_xl[MAX_N * HH];
__device__ float  g_xr[MAX_N * HH];
__device__ float  g_A [MAX_N * HH];
__device__ float  g_B [MAX_N * HH];
__device__ float  g_pacc[MAX_N * GSPLIT * HH];     // gat partials
__device__ float  g_pden[MAX_N * GSPLIT * NHEADS];
__device__ __align__(16) __nv_bfloat16 g_w2h[128 * 256];   // W2^T hi  [n][k]
__device__ __align__(16) __nv_bfloat16 g_w2l[128 * 256];   // W2^T lo
__device__ __align__(16) __nv_bfloat16 g_hh[MAX_N * HH];   // h hi/lo split
__device__ __align__(16) __nv_bfloat16 g_hl[MAX_N * HH];
__device__ __align__(16) __nv_bfloat16 g_wth[5 * 512 * HH]; // W^T hi: 4 layers
__device__ __align__(16) __nv_bfloat16 g_wtl[5 * 512 * HH]; //  (Wl|Wr) + (p1a|p1b)

// bf16 HMMA (sm_80+, no arch-feature suffix -> compiles for base sm_103)
__device__ __forceinline__ void mma16816(float* d, const uint32_t* a,
                                         uint32_t b0, uint32_t b1) {
    asm volatile(
        "mma.sync.aligned.m16n8k16.row.col.f32.bf16.bf16.f32 "
        "{%0,%1,%2,%3}, {%4,%5,%6,%7}, {%8,%9}, {%0,%1,%2,%3};"
        : "+f"(d[0]), "+f"(d[1]), "+f"(d[2]), "+f"(d[3])
        : "r"(a[0]), "r"(a[1]), "r"(a[2]), "r"(a[3]), "r"(b0), "r"(b1));
}
// ldmatrix x4: one instruction loads a 16x16 bf16 fragment (4 8x8 tiles)
__device__ __forceinline__ void ldmx4(uint32_t* r, const void* p) {
    uint32_t a = (uint32_t)__cvta_generic_to_shared(p);
    asm volatile("ldmatrix.sync.aligned.m8n8.x4.shared.b16 {%0,%1,%2,%3}, [%4];"
                 : "=r"(r[0]), "=r"(r[1]), "=r"(r[2]), "=r"(r[3]) : "r"(a));
}

// ---------------- setup kernels ------------------------------------------------
__global__ void k_embinit(const float* __restrict__ x, const float* __restrict__ W,
                          const float* __restrict__ b) {
    int n = blockIdx.x, t = threadIdx.x;
    float hv = x[n] * W[t] + b[t];
    g_h[n * HH + t] = hv;
    __nv_bfloat16 hi = __float2bfloat16(hv);
    g_hh[n * HH + t] = hi;
    g_hl[n * HH + t] = __float2bfloat16(hv - __bfloat162float(hi));
    if (t < SUB) g_cnt2[n * SUB + t] = 0;
    if (t == 32) { g_deg1[n] = 0; g_deg2[n] = 0; }
    if (t == 33) {
        g_asum[3 * n] = 0.f; g_asum[3 * n + 1] = 0.f; g_asum[3 * n + 2] = 0.f;
    }
}

__global__ void k_edge_stats(const int* __restrict__ ei, const float* __restrict__ ea,
                             int E) {
    int e = blockIdx.x * blockDim.x + threadIdx.x;
    if (e >= E) return;
    int s = ei[e], d = ei[E + e];
    float a0 = ea[3 * e], a1 = ea[3 * e + 1], a2 = ea[3 * e + 2];
    atomicAdd(&g_cnt2[d * SUB + (e & (SUB - 1))], 1);
    atomicAdd(&g_asum[3 * d + 0], a0);
    atomicAdd(&g_asum[3 * d + 1], a1);
    atomicAdd(&g_asum[3 * d + 2], a2);
    int best = 0; float bv = a0;
    if (a1 > bv) { best = 1; bv = a1; }
    if (a2 > bv) { best = 2; }
    if (best == 1) { atomicAdd(&g_deg1[s], 1); atomicAdd(&g_deg1[d], 1); }
    else if (best == 2) { atomicAdd(&g_deg2[s], 1); atomicAdd(&g_deg2[d], 1); }
}

__global__ void k_scan(int N) {
    __shared__ int sc[1024];
    int t = threadIdx.x;
    int4 v[8];
    int cnt = 0;
    if (t < N) {
        const int4* p = (const int4*)(g_cnt2 + t * SUB);
#pragma unroll
        for (int i = 0; i < 8; i++) v[i] = p[i];
#pragma unroll
        for (int i = 0; i < 8; i++) cnt += v[i].x + v[i].y + v[i].z + v[i].w;
    }
    int len = (t < N) ? (cnt + 1) : 0;
    sc[t] = len;
    __syncthreads();
    for (int off = 1; off < 1024; off <<= 1) {
        int u = (t >= off) ? sc[t - off] : 0;
        __syncthreads();
        sc[t] += u;
        __syncthreads();
    }
    if (t < N) {
        int incl = sc[t];
        int excl = incl - len;
        g_roff[t + 1] = incl;
        if (t == 0) g_roff[0] = 0;
        int off = excl;
        int4* q = (int4*)(g_cur2 + t * SUB);
#pragma unroll
        for (int i = 0; i < 8; i++) {
            int4 o;
            o.x = off; off += v[i].x;
            o.y = off; off += v[i].y;
            o.z = off; off += v[i].z;
            o.w = off; off += v[i].w;
            q[i] = o;
        }
        int slot = excl + cnt;
        float c = fmaxf((float)cnt, 1.0f);
        g_epack[slot] = make_float4(__int_as_float(t),
                                    g_asum[3 * t + 0] / c,
                                    g_asum[3 * t + 1] / c,
                                    g_asum[3 * t + 2] / c);
    }
}

__global__ void k_scatter(const int* __restrict__ ei, const float* __restrict__ ea,
                          int E) {
    int e = blockIdx.x * blockDim.x + threadIdx.x;
    if (e >= E) return;
    int s = ei[e], d = ei[E + e];
    int pos = atomicAdd(&g_cur2[d * SUB + (e & (SUB - 1))], 1);
    g_epack[pos] = make_float4(__int_as_float(s), ea[3 * e], ea[3 * e + 1], ea[3 * e + 2]);
}

// W2^T bf16 hi/lo split: g_w2h/l[n][k] = split(p2W[k][n])
__global__ void k_wsplit(const float* __restrict__ p2W) {
    int n = blockIdx.x, k = threadIdx.x;
    float w = p2W[k * 128 + n];
    __nv_bfloat16 hi = __float2bfloat16(w);
    g_w2h[n * 256 + k] = hi;
    g_w2l[n * 256 + k] = __float2bfloat16(w - __bfloat162float(hi));
}

// split all node-linear weights (transposed [n][k]) into bf16 hi/lo:
// slot l<4: cols = (Wl[l] | Wr[l]); slot 4: cols = (p1W[:256] | p1W[256:])
__global__ void k_wsplit_all(const float* __restrict__ Wl,
                             const float* __restrict__ Wr,
                             const float* __restrict__ p1W) {
    int n = blockIdx.x, l = blockIdx.y, k = threadIdx.x;
    float w;
    if (l < 4) {
        w = (n < 256) ? Wl[((size_t)l * 256 + k) * 256 + n]
                      : Wr[((size_t)l * 256 + k) * 256 + (n - 256)];
    } else {
        w = (n < 256) ? p1W[(size_t)k * 256 + n]
                      : p1W[(size_t)(k + 256) * 256 + (n - 256)];
    }
    __nv_bfloat16 hi = __float2bfloat16(w);
    size_t idx = ((size_t)l * 512 + n) * HH + k;
    g_wth[idx] = hi;
    g_wtl[idx] = __float2bfloat16(w - __bfloat162float(hi));
}

// ---------------- node linear layers via bf16-split HMMA ----------------------
// out[m][n] (128x128 tile) = H[m][:] . W^T[n][:]  (3-term hi/lo split) + bias.
// outsel: 0 -> (g_xl | g_xr), 1 -> (g_A | g_B).
#define QSTR 40   // padded bf16 row stride (80B: conflict-free, 16B-aligned)
__global__ void __launch_bounds__(256)
k_lin_mma(int wslot, int outsel,
          const float* __restrict__ b0, const float* __restrict__ b1, int N) {
    __shared__ __align__(16) __nv_bfloat16 Ah[128][QSTR], Al[128][QSTR];
    __shared__ __align__(16) __nv_bfloat16 Wh[128][QSTR], Wlo[128][QSTR];
    int t = threadIdx.x;
    int lane = t & 31, wid = t >> 5;
    int warp_m = wid & 3, warp_n = wid >> 2;
    int mbase = warp_m * 32, nbase = warp_n * 64;
    int tm = blockIdx.x, tn = blockIdx.y;
    float* outp = (outsel == 0) ? ((tn < 2) ? g_xl : g_xr)
                                : ((tn < 2) ? g_A  : g_B);
    const float* bp = (tn < 2) ? b0 : b1;
    int ncb = (tn & 1) * 128;

    int pr = t >> 1, kh = t & 1;
    int hrow = tm * 128 + pr;
    if (hrow > N - 1) hrow = N - 1;
    const __nv_bfloat16* wrh = &g_wth[((size_t)wslot * 512 + tn * 128 + pr) * HH];
    const __nv_bfloat16* wrl = &g_wtl[((size_t)wslot * 512 + tn * 128 + pr) * HH];
    int lrow = lane & 15;                 // ldmatrix row within 16x16 fragment
    int lcol = (lane >> 4) << 3;          // 0 or 8

    float acc[2][8][4] = {};
    for (int cc = 0; cc < 8; cc++) {
        __syncthreads();
        int cb = cc * 32 + kh * 16;
        const uint2* ah = (const uint2*)&g_hh[(size_t)hrow * HH + cb];
        const uint2* al = (const uint2*)&g_hl[(size_t)hrow * HH + cb];
        const uint2* wh = (const uint2*)&wrh[cb];
        const uint2* wl = (const uint2*)&wrl[cb];
#pragma unroll
        for (int m = 0; m < 4; m++) {
            *(uint2*)&Ah[pr][kh * 16 + 4 * m]  = ah[m];
            *(uint2*)&Al[pr][kh * 16 + 4 * m]  = al[m];
            *(uint2*)&Wh[pr][kh * 16 + 4 * m]  = wh[m];
            *(uint2*)&Wlo[pr][kh * 16 + 4 * m] = wl[m];
        }
        __syncthreads();
#pragma unroll
        for (int k0 = 0; k0 < 32; k0 += 16) {
            uint32_t fah[2][4], fal[2][4];
#pragma unroll
            for (int mt = 0; mt < 2; mt++) {
                ldmx4(fah[mt], &Ah[mbase + mt * 16 + lrow][k0 + lcol]);
                ldmx4(fal[mt], &Al[mbase + mt * 16 + lrow][k0 + lcol]);
            }
#pragma unroll
            for (int ntp = 0; ntp < 4; ntp++) {
                uint32_t bh[4], blo[4];
                ldmx4(bh,  &Wh [nbase + ntp * 16 + lrow][k0 + lcol]);
                ldmx4(blo, &Wlo[nbase + ntp * 16 + lrow][k0 + lcol]);
#pragma unroll
                for (int sb = 0; sb < 2; sb++) {
                    int nt = 2 * ntp + sb;
#pragma unroll
                    for (int mt = 0; mt < 2; mt++) {
                        mma16816(acc[mt][nt], fah[mt], bh[sb],  bh[2 + sb]);
                        mma16816(acc[mt][nt], fah[mt], blo[sb], blo[2 + sb]);
                        mma16816(acc[mt][nt], fal[mt], bh[sb],  bh[2 + sb]);
                    }
                }
            }
        }
    }

    int rg = lane >> 2;
#pragma unroll
    for (int nt = 0; nt < 8; nt++) {
        int col = ncb + nbase + nt * 8 + (lane & 3) * 2;
        float bv0 = bp ? bp[col] : 0.f;
        float bv1 = bp ? bp[col + 1] : 0.f;
#pragma unroll
        for (int mt = 0; mt < 2; mt++) {
            int r0 = tm * 128 + mbase + mt * 16 + rg;
            if (r0 < N)
                *(float2*)&outp[(size_t)r0 * HH + col] =
                    make_float2(acc[mt][nt][0] + bv0, acc[mt][nt][1] + bv1);
            int r1 = r0 + 8;
            if (r1 < N)
                *(float2*)&outp[(size_t)r1 * HH + col] =
                    make_float2(acc[mt][nt][2] + bv0, acc[mt][nt][3] + bv1);
        }
    }
}

// GAT partial: grid (N, GSPLIT). Pure sums (no running max) -> partials combine.
__global__ void __launch_bounds__(128)
k_gatp(const float* __restrict__ We, const float* __restrict__ att, int l) {
    __shared__ float4 ep[ETILE];
    int n = blockIdx.x, sp = blockIdx.y, t = threadIdx.x;
    int lane = t & 31;
    int ch0 = 2 * t;
    int head = t >> 4;
    int hc = ch0 & 31;
    float2 xr2 = *(const float2*)&g_xr[n * HH + ch0];
    float att0 = att[(l * NHEADS + head) * 32 + hc];
    float att1 = att[(l * NHEADS + head) * 32 + hc + 1];
    float we00 = We[(l * 3 + 0) * HH + ch0], we01 = We[(l * 3 + 0) * HH + ch0 + 1];
    float we10 = We[(l * 3 + 1) * HH + ch0], we11 = We[(l * 3 + 1) * HH + ch0 + 1];
    float we20 = We[(l * 3 + 2) * HH + ch0], we21 = We[(l * 3 + 2) * HH + ch0 + 1];
    int r0 = g_roff[n], cnt_all = g_roff[n + 1] - r0;
    int e0 = r0 + (cnt_all * sp) / GSPLIT;
    int e1 = r0 + (cnt_all * (sp + 1)) / GSPLIT;

    float den = 0.f, acc0 = 0.f, acc1 = 0.f;
    for (int t0 = e0; t0 < e1; t0 += ETILE) {
        int cnt = min(ETILE, e1 - t0);
        __syncthreads();
        for (int k = t; k < cnt; k += 128) ep[k] = g_epack[t0 + k];
        __syncthreads();
#pragma unroll 2
        for (int g = 0; g < cnt; g += 4) {
            float2 xv[4];
            float al[4];
#pragma unroll
            for (int u = 0; u < 4; u++) {
                int idx = min(g + u, cnt - 1);
                float4 e = ep[idx];
                int s = __float_as_int(e.x);
                xv[u] = *(const float2*)&g_xl[s * HH + ch0];
                float s0 = xv[u].x + xr2.x + e.y * we00 + e.z * we10 + e.w * we20;
                float s1 = xv[u].y + xr2.y + e.y * we01 + e.z * we11 + e.w * we21;
                s0 = s0 > 0.f ? s0 : 0.2f * s0;
                s1 = s1 > 0.f ? s1 : 0.2f * s1;
                float v = s0 * att0 + s1 * att1;
                al[u] = (g + u < cnt) ? v : -1e30f;
            }
            float p0 = (lane & 8) ? al[2] : al[0];
            float q0 = (lane & 8) ? al[0] : al[2];
            float p1 = (lane & 8) ? al[3] : al[1];
            float q1 = (lane & 8) ? al[1] : al[3];
            p0 += __shfl_xor_sync(0xffffffffu, q0, 8);
            p1 += __shfl_xor_sync(0xffffffffu, q1, 8);
            float pa = (lane & 4) ? p1 : p0;
            float qa = (lane & 4) ? p0 : p1;
            pa += __shfl_xor_sync(0xffffffffu, qa, 4);
            pa += __shfl_xor_sync(0xffffffffu, pa, 2);
            pa += __shfl_xor_sync(0xffffffffu, pa, 1);
            float wexp = __expf(pa);                // 1 exp, then broadcast
            int base = lane & 16;
#pragma unroll
            for (int u = 0; u < 4; u++) {
                float w = __shfl_sync(0xffffffffu, wexp, base + (u << 2));
                den += w;
                acc0 = fmaf(w, xv[u].x, acc0);
                acc1 = fmaf(w, xv[u].y, acc1);
            }
        }
    }
    int pb = n * GSPLIT + sp;
    *(float2*)&g_pacc[pb * HH + ch0] = make_float2(acc0, acc1);
    if ((t & 15) == 0) g_pden[pb * NHEADS + head] = den;
}

// GAT combine: sum GSPLIT partials, normalize, residual + LayerNorm + ReLU.
// Also writes the bf16 hi/lo split of the new h for the next linear layer.
__global__ void __launch_bounds__(128)
k_gatc(const float* __restrict__ gb, const float* __restrict__ lng,
       const float* __restrict__ lnb, int l) {
    __shared__ float red[4];
    int n = blockIdx.x, t = threadIdx.x;
    int wid = t >> 5, lane = t & 31;
    int ch0 = 2 * t;
    int head = t >> 4;
    float acc0 = 0.f, acc1 = 0.f, den = 0.f;
#pragma unroll
    for (int s = 0; s < GSPLIT; s++) {
        int pb = n * GSPLIT + s;
        float2 a = *(const float2*)&g_pacc[pb * HH + ch0];
        acc0 += a.x; acc1 += a.y;
        den += g_pden[pb * NHEADS + head];
    }
    float inv = 1.0f / den;
    float2 hres = *(const float2*)&g_h[n * HH + ch0];
    float o0 = acc0 * inv + gb[l * HH + ch0]     + hres.x;
    float o1 = acc1 * inv + gb[l * HH + ch0 + 1] + hres.y;

    float v = o0 + o1;
#pragma unroll
    for (int o = 16; o > 0; o >>= 1) v += __shfl_xor_sync(0xffffffffu, v, o);
    if (lane == 0) red[wid] = v;
    __syncthreads();
    float mu = (red[0] + red[1] + red[2] + red[3]) * (1.0f / HH);
    float d0 = o0 - mu, d1 = o1 - mu;
    float q = d0 * d0 + d1 * d1;
#pragma unroll
    for (int o = 16; o > 0; o >>= 1) q += __shfl_xor_sync(0xffffffffu, q, o);
    __syncthreads();
    if (lane == 0) red[wid] = q;
    __syncthreads();
    float var = (red[0] + red[1] + red[2] + red[3]) * (1.0f / HH);
    float rstd = rsqrtf(var + 1e-5f);
    float y0 = fmaxf(d0 * rstd * lng[l * HH + ch0]     + lnb[l * HH + ch0], 0.f);
    float y1 = fmaxf(d1 * rstd * lng[l * HH + ch0 + 1] + lnb[l * HH + ch0 + 1], 0.f);
    *(float2*)&g_h[n * HH + ch0] = make_float2(y0, y1);
    __nv_bfloat16 h0 = __float2bfloat16(y0), h1 = __float2bfloat16(y1);
    __nv_bfloat162 hh; hh.x = h0; hh.y = h1;
    *(__nv_bfloat162*)&g_hh[n * HH + ch0] = hh;
    __nv_bfloat162 hl;
    hl.x = __float2bfloat16(y0 - __bfloat162float(h0));
    hl.y = __float2bfloat16(y1 - __bfloat162float(h1));
    *(__nv_bfloat162*)&g_hl[n * HH + ch0] = hl;
}

// graph pooling + value head + Potts energy
__global__ void k_graph(const float* __restrict__ v1W, const float* __restrict__ v1b,
                        const float* __restrict__ v2W, const float* __restrict__ v2b,
                        const float* __restrict__ coup, float* __restrict__ out,
                        int N, long long P) {
    __shared__ float gr[2 * HH];
    __shared__ float psum[2][HH];
    __shared__ float pmax[2][HH];
    __shared__ float sred[512];
    int t = threadIdx.x;
    int half = t >> 8, ch = t & 255;
    int nh = N >> 1;
    {
        float s = 0.f, mx = -1e30f;
        for (int n = half * nh; n < (half + 1) * nh; n++) {
            float v = g_h[n * HH + ch];
            s += v; mx = fmaxf(mx, v);
        }
        psum[half][ch] = s; pmax[half][ch] = mx;
    }
    __syncthreads();
    if (t < HH) {
        gr[t] = (psum[0][t] + psum[1][t]) / (float)N;
        gr[HH + t] = fmaxf(pmax[0][t], pmax[1][t]);
    }
    __syncthreads();
    float contrib = 0.f;
    if (t < HH) {
        float a = v1b[t];
        for (int c = 0; c < 2 * HH; c++) a = fmaf(gr[c], v1W[c * HH + t], a);
        a = fmaxf(a, 0.f);
        contrib = a * v2W[t];
    }
    sred[t] = contrib;
    __syncthreads();
    for (int off = 256; off > 0; off >>= 1) {
        if (t < off) sred[t] += sred[t + off];
        __syncthreads();
    }
    if (t == 0) out[P] = sred[0] + v2b[0];

    float e = 0.f;
    for (int n = t; n < N; n += 512) {
        float d1 = (float)g_deg1[n], d2 = (float)g_deg2[n];
        e += d1 * d1 + d2 * d2;
    }
    __syncthreads();
    sred[t] = e;
    __syncthreads();
    for (int off = 256; off > 0; off >>= 1) {
        if (t < off) sred[t] += sred[t + off];
        __syncthreads();
    }
    if (t == 0) out[P + 1] = coup[0] * sred[0] / (2.0f * (float)N);
}

// ---------------- all-pairs MLP via bf16-split warp MMA (HMMA + ldmatrix) ------
// (R15 configuration: 8 k-chunks of 32, measured best in-graph)
__global__ void __launch_bounds__(256)
k_pairs_mma(const float* __restrict__ p2b, const float* __restrict__ p3W,
            const float* __restrict__ p3b, float* __restrict__ out,
            int N, long long P) {
    __shared__ __align__(16) __nv_bfloat16 Qh[128][QSTR], Ql[128][QSTR];
    __shared__ __align__(16) __nv_bfloat16 Wh[128][QSTR], Wl[128][QSTR];
    __shared__ int si[128], sj[128];
    __shared__ float eps[128][2];
    int t = threadIdx.x;
    int lane = t & 31, wid = t >> 5;
    int warp_m = wid & 3, warp_n = wid >> 2;
    int mbase = warp_m * 32, nbase = warp_n * 64;
    long long pbase = (long long)blockIdx.x * 128;

    if (t < 128) {
        long long p = pbase + t;
        if (p > P - 1) p = P - 1;
        float tn = 2.0f * N - 1.0f;
        float disc = fmaxf(tn * tn - 8.0f * (float)p, 0.0f);
        int i = (int)((tn - sqrtf(disc)) * 0.5f);
        if (i < 0) i = 0;
        if (i > N - 2) i = N - 2;
        while ((long long)(i + 1) * (2 * N - 2 - i) / 2 <= p) i++;
        while ((long long)i * (2 * N - 1 - i) / 2 > p) i--;
        int j = i + 1 + (int)(p - (long long)i * (2 * N - 1 - i) / 2);
        si[t] = i; sj[t] = j;
    }
    __syncthreads();

    int pr = t >> 1, kh = t & 1;
    size_t ib = (size_t)si[pr] * HH;
    size_t jb = (size_t)sj[pr] * HH;
    int lrow = lane & 15;
    int lcol = (lane >> 4) << 3;

    float acc[2][8][4] = {};
    for (int cc = 0; cc < 8; cc++) {
        __syncthreads();
        int cb = cc * 32 + kh * 16;
#pragma unroll
        for (int m = 0; m < 4; m++) {
            float4 a4 = *(const float4*)&g_A[ib + cb + 4 * m];
            float4 b4 = *(const float4*)&g_B[jb + cb + 4 * m];
            float q0 = fmaxf(a4.x + b4.x, 0.f), q1 = fmaxf(a4.y + b4.y, 0.f);
            float q2 = fmaxf(a4.z + b4.z, 0.f), q3 = fmaxf(a4.w + b4.w, 0.f);
            __nv_bfloat162 h01 = __floats2bfloat162_rn(q0, q1);
            __nv_bfloat162 h23 = __floats2bfloat162_rn(q2, q3);
            __nv_bfloat162 l01 = __floats2bfloat162_rn(
                q0 - __bfloat162float(h01.x), q1 - __bfloat162float(h01.y));
            __nv_bfloat162 l23 = __floats2bfloat162_rn(
                q2 - __bfloat162float(h23.x), q3 - __bfloat162float(h23.y));
            uint2 uh, ul;
            uh.x = *(uint32_t*)&h01; uh.y = *(uint32_t*)&h23;
            ul.x = *(uint32_t*)&l01; ul.y = *(uint32_t*)&l23;
            *(uint2*)&Qh[pr][kh * 16 + 4 * m] = uh;
            *(uint2*)&Ql[pr][kh * 16 + 4 * m] = ul;
        }
        {
            const uint2* sh = (const uint2*)&g_w2h[(size_t)pr * 256 + cb];
            const uint2* sl = (const uint2*)&g_w2l[(size_t)pr * 256 + cb];
#pragma unroll
            for (int m = 0; m < 4; m++) {
                *(uint2*)&Wh[pr][kh * 16 + 4 * m] = sh[m];
                *(uint2*)&Wl[pr][kh * 16 + 4 * m] = sl[m];
            }
        }
        __syncthreads();
#pragma unroll
        for (int k0 = 0; k0 < 32; k0 += 16) {
            uint32_t ah[2][4], al[2][4];
#pragma unroll
            for (int mt = 0; mt < 2; mt++) {
                ldmx4(ah[mt], &Qh[mbase + mt * 16 + lrow][k0 + lcol]);
                ldmx4(al[mt], &Ql[mbase + mt * 16 + lrow][k0 + lcol]);
            }
#pragma unroll
            for (int ntp = 0; ntp < 4; ntp++) {
                uint32_t bh[4], blo[4];
                ldmx4(bh,  &Wh[nbase + ntp * 16 + lrow][k0 + lcol]);
                ldmx4(blo, &Wl[nbase + ntp * 16 + lrow][k0 + lcol]);
#pragma unroll
                for (int sb = 0; sb < 2; sb++) {
                    int nt = 2 * ntp + sb;
#pragma unroll
                    for (int mt = 0; mt < 2; mt++) {
                        mma16816(acc[mt][nt], ah[mt], bh[sb],  bh[2 + sb]);
                        mma16816(acc[mt][nt], ah[mt], blo[sb], blo[2 + sb]);
                        mma16816(acc[mt][nt], al[mt], bh[sb],  bh[2 + sb]);
                    }
                }
            }
        }
    }

    float pA0 = 0.f, pA1 = 0.f, pB0 = 0.f, pB1 = 0.f;
#pragma unroll
    for (int nt = 0; nt < 8; nt++) {
#pragma unroll
        for (int v = 0; v < 2; v++) {
            int col = nbase + nt * 8 + (lane & 3) * 2 + v;
            float b2 = p2b[col], w3 = p3W[col];
            pA0 = fmaf(fmaxf(acc[0][nt][v] + b2, 0.f), w3, pA0);
            pB0 = fmaf(fmaxf(acc[0][nt][2 + v] + b2, 0.f), w3, pB0);
            pA1 = fmaf(fmaxf(acc[1][nt][v] + b2, 0.f), w3, pA1);
            pB1 = fmaf(fmaxf(acc[1][nt][2 + v] + b2, 0.f), w3, pB1);
        }
    }
    pA0 += __shfl_xor_sync(0xffffffffu, pA0, 1);
    pA0 += __shfl_xor_sync(0xffffffffu, pA0, 2);
    pB0 += __shfl_xor_sync(0xffffffffu, pB0, 1);
    pB0 += __shfl_xor_sync(0xffffffffu, pB0, 2);
    pA1 += __shfl_xor_sync(0xffffffffu, pA1, 1);
    pA1 += __shfl_xor_sync(0xffffffffu, pA1, 2);
    pB1 += __shfl_xor_sync(0xffffffffu, pB1, 1);
    pB1 += __shfl_xor_sync(0xffffffffu, pB1, 2);
    if ((lane & 3) == 0) {
        int g = lane >> 2;
        eps[mbase + g][warp_n]      = pA0;
        eps[mbase + g + 8][warp_n]  = pB0;
        eps[mbase + g + 16][warp_n] = pA1;
        eps[mbase + g + 24][warp_n] = pB1;
    }
    __syncthreads();
    if (t < 128) {
        long long pw = pbase + t;
        if (pw < P) out[pw] = eps[t][0] + eps[t][1] + p3b[0];
    }
}

// ---------------- launch ------------------------------------------------------
extern "C" void kernel_launch(void* const* d_in, const int* in_sizes, int n_in,
                              void* d_out, int out_size) {
    const float* x    = (const float*)d_in[0];
    const int*   ei   = (const int*)  d_in[1];
    const float* ea   = (const float*)d_in[2];
    const float* embW = (const float*)d_in[3];
    const float* embB = (const float*)d_in[4];
    const float* Wl   = (const float*)d_in[5];
    const float* bl   = (const float*)d_in[6];
    const float* Wr   = (const float*)d_in[7];
    const float* br   = (const float*)d_in[8];
    const float* We   = (const float*)d_in[9];
    const float* att  = (const float*)d_in[10];
    const float* gb   = (const float*)d_in[11];
    const float* lng  = (const float*)d_in[12];
    const float* lnb  = (const float*)d_in[13];
    const float* p1W  = (const float*)d_in[14];
    const float* p1b  = (const float*)d_in[15];
    const float* p2W  = (const float*)d_in[16];
    const float* p2b  = (const float*)d_in[17];
    const float* p3W  = (const float*)d_in[18];
    const float* p3b  = (const float*)d_in[19];
    const float* v1W  = (const float*)d_in[20];
    const float* v1b  = (const float*)d_in[21];
    const float* v2W  = (const float*)d_in[22];
    const float* v2b  = (const float*)d_in[23];
    const float* coup = (const float*)d_in[24];

    int N = in_sizes[0];
    int E = in_sizes[1] / 2;
    long long P = (long long)N * (N - 1) / 2;
    float* out = (float*)d_out;

    int rtiles = (N + 127) / 128;
    dim3 ling(rtiles, 4);

    k_embinit<<<N, 256>>>(x, embW, embB);
    k_edge_stats<<<(E + 255) / 256, 256>>>(ei, ea, E);
    k_scan<<<1, 1024>>>(N);
    k_scatter<<<(E + 255) / 256, 256>>>(ei, ea, E);
    k_wsplit_all<<<dim3(512, 5), 256>>>(Wl, Wr, p1W);
    k_wsplit<<<128, 256>>>(p2W);
    k_lin_mma<<<ling, 256>>>(0, 0, bl, br, N);
    for (int l = 0; l < 4; l++) {
        k_gatp<<<dim3(N, GSPLIT), 128>>>(We, att, l);
        k_gatc<<<N, 128>>>(gb, lng, lnb, l);
        if (l < 3)
            k_lin_mma<<<ling, 256>>>(l + 1, 0, bl + (l + 1) * HH,
                                     br + (l + 1) * HH, N);
    }
    k_graph<<<1, 512>>>(v1W, v1b, v2W, v2b, coup, out, N, P);
    k_lin_mma<<<ling, 256>>>(4, 1, p1b, (const float*)nullptr, N);
    int pblocks = (int)((P + 127) / 128);
    k_pairs_mma<<<pblocks, 256>>>(p2b, p3W, p3b, out, N, P);
}